// round 11
// baseline (speedup 1.0000x reference)
#include <cuda_runtime.h>
#include <math.h>
#include <stdint.h>

// ---------------- problem constants ----------------
#define D1      512
#define D2      1024
#define SEQLEN  4096
#define CHUNK   256
#define NCHUNK  16
#define BATCH   4
#define NROWS   (BATCH*CHUNK)          // 1024 rows per chunk
#define TOTROWS (BATCH*SEQLEN)         // 16384
#define LOSS_SCALE (2.0f/((float)NROWS*(float)D1))

// ---------------- device scratch ----------------
__device__ float g_W1 [D1*D2];
__device__ float g_W2a[D2*D1];         // W2 ping
__device__ float g_W2b[D2*D1];         // W2 pong
__device__ float g_S1 [D1*D2];
__device__ float g_S2 [D2*D1];
__device__ float g_WKV[D1*D2];
__device__ float g_kv [NCHUNK*NROWS*D2];   // chunk-major: [c][b][r][D2]; 0..511=k, 512..1023=v
__device__ float g_h  [NROWS*D2];
__device__ float g_a  [NROWS*D2];
__device__ float g_dp [NROWS*D1];
__device__ float g_dh [NROWS*D2];
__device__ float g_q  [TOTROWS*D1];
__device__ float g_aq [TOTROWS*D2];

// ---------------- math helpers ----------------
__device__ __forceinline__ float gelu_f(float x) {
    return 0.5f * x * (1.0f + erff(x * 0.70710678118654752f));
}
__device__ __forceinline__ float gelu_grad(float x) {
    float cdf = 0.5f * (1.0f + erff(x * 0.70710678118654752f));
    float pdf = 0.3989422804014327f * expf(-0.5f * x * x);
    return cdf + x * pdf;
}
__device__ __forceinline__ float sigmoid_f(float x) { return 1.0f / (1.0f + expf(-x)); }

__device__ __forceinline__ void split_tf32(float v, uint32_t& hi, uint32_t& lo) {
    uint32_t h;
    asm("cvt.rna.tf32.f32 %0, %1;" : "=r"(h) : "f"(v));
    float lf = v - __uint_as_float(h);
    asm("cvt.rna.tf32.f32 %0, %1;" : "=r"(lo) : "f"(lf));
    hi = h;
}
__device__ __forceinline__ void mma_tf32(float* c, const uint32_t* a, const uint32_t* b) {
    asm volatile(
        "mma.sync.aligned.m16n8k8.row.col.f32.tf32.tf32.f32 "
        "{%0,%1,%2,%3}, {%4,%5,%6,%7}, {%8,%9}, {%0,%1,%2,%3};"
        : "+f"(c[0]), "+f"(c[1]), "+f"(c[2]), "+f"(c[3])
        : "r"(a[0]), "r"(a[1]), "r"(a[2]), "r"(a[3]), "r"(b[0]), "r"(b[1]));
}

// cp.async helper (16B only — all staging paths are 16-byte now)
__device__ __forceinline__ void cp16(void* s, const void* g) {
    uint32_t sa = (uint32_t)__cvta_generic_to_shared(s);
    asm volatile("cp.async.ca.shared.global [%0], [%1], 16;\n" :: "r"(sa), "l"(g));
}
#define CP_COMMIT() asm volatile("cp.async.commit_group;\n" ::: "memory")
#define CP_WAIT(n)  asm volatile("cp.async.wait_group %0;\n" :: "n"(n) : "memory")

// ---------------- init ----------------
__global__ void init_kernel(const float* __restrict__ mw1, const float* __restrict__ mw2,
                            const float* __restrict__ wk,  const float* __restrict__ wv) {
    int i = blockIdx.x * blockDim.x + threadIdx.x;
    if (i < D1 * D2) {
        g_W1[i]  = mw1[i];  g_S1[i] = 0.0f;
        g_W2a[i] = mw2[i];  g_S2[i] = 0.0f;
        int d = i / D2, j = i % D2;
        g_WKV[i] = (j < D1) ? wk[d * D1 + j] : wv[d * D1 + (j - D1)];
    }
}

// ---------------- tiling ----------------
#define BM 64
#define BN 64
#define BK 32
// SMEM tile footprint: 2304 words either orientation.
//  A !TA: [m][k] pitch 36 (frag banks 4g+t4 distinct)   A TA: [k][m] pitch 72 (frag banks 8t4+g distinct)
//  B !TB: [k][n] pitch 72 (frag banks 8t4+g distinct)   B TB: [n][k] pitch 36 (frag banks 4g+t4 distinct)
#define TILE_WORDS 2304

// ---------------- GEMM: 3xTF32, cp.async double buffer, transpose-aware layouts ----------------
// op(A)[M,K] * op(B)[K,N]
// EPI: 0 C=acc | 1 C=acc, aux3=gelu(acc) | 2 C=(acc-aux1)*LOSS_SCALE | 3 C=acc*gelu'(aux1)
//      4 S(aux3)=decay*S-lr*acc; Wnew(aux4)=(1-a)*Wold(aux1)+S | 5 C=gelu(acc) | 6 kv chunk-major permute
template<bool TA, bool TB, int EPI>
__global__ __launch_bounds__(128)
void gemm3(const float* __restrict__ A, const float* __restrict__ B, float* __restrict__ C,
           int K, int lda, int ldb, int ldc, int ldaux,
           const float* __restrict__ aux1, float* __restrict__ aux3, float* __restrict__ aux4,
           const float* __restrict__ pa, const float* __restrict__ pl, const float* __restrict__ pd,
           int cidx) {
    __shared__ __align__(16) float As[2][TILE_WORDS];
    __shared__ __align__(16) float Bs[2][TILE_WORDS];

    int by = blockIdx.y;
    if constexpr (EPI == 6) by = (by >> 2) * 64 + cidx * 4 + (by & 3);  // rows of chunk cidx
    const int row0 = by * BM;
    const int col0 = blockIdx.x * BN;
    const int t    = threadIdx.x;
    const int lane = t & 31;
    const int warp = t >> 5;
    const int warpRow = (warp >> 1) * 32;
    const int warpCol = (warp & 1) * 32;
    const int g  = lane >> 2;
    const int t4 = lane & 3;

    // SMEM index helpers (template-constant selection)
    auto aIdx = [&](int m, int k) -> int { return TA ? (k * 72 + m) : (m * 36 + k); };
    auto bIdx = [&](int k, int n) -> int { return TB ? (n * 36 + k) : (k * 72 + n); };

    auto stage = [&](int b, int k0) {
        #pragma unroll
        for (int it = 0; it < 4; it++) {
            int f = t + it * 128;
            if constexpr (!TA) {
                int m = f >> 3, kk0 = (f & 7) * 4;          // A row-major: 4 consecutive k
                cp16(&As[b][m * 36 + kk0], &A[(size_t)(row0 + m) * lda + (k0 + kk0)]);
            } else {
                int kk = f >> 4, m0 = (f & 15) * 4;         // A stored [K][lda]: 4 consecutive m
                cp16(&As[b][kk * 72 + m0], &A[(size_t)(k0 + kk) * lda + (row0 + m0)]);
            }
        }
        #pragma unroll
        for (int it = 0; it < 4; it++) {
            int f = t + it * 128;
            if constexpr (!TB) {
                int kk = f >> 4, n0 = (f & 15) * 4;         // B row-major: 4 consecutive n
                cp16(&Bs[b][kk * 72 + n0], &B[(size_t)(k0 + kk) * ldb + (col0 + n0)]);
            } else {
                int n = f >> 3, kk0 = (f & 7) * 4;          // B stored [N][ldb]: 4 consecutive k
                cp16(&Bs[b][n * 36 + kk0], &B[(size_t)(col0 + n) * ldb + (k0 + kk0)]);
            }
        }
    };

    float acc[2][4][4];
    #pragma unroll
    for (int i = 0; i < 2; i++)
        #pragma unroll
        for (int j = 0; j < 4; j++)
            #pragma unroll
            for (int r = 0; r < 4; r++) acc[i][j][r] = 0.0f;

    const int KITER = K / BK;
    stage(0, 0);
    CP_COMMIT();
    int buf = 0;
    for (int it = 0; it < KITER; ++it) {
        if (it + 1 < KITER) {
            stage(buf ^ 1, (it + 1) * BK);
            CP_COMMIT();
            CP_WAIT(1);
        } else {
            CP_WAIT(0);
        }
        __syncthreads();

        #pragma unroll
        for (int ks = 0; ks < 4; ks++) {
            const int kc = ks * 8 + t4;
            uint32_t ah[2][4], al[2][4], bh[4][2], bl[4][2];
            #pragma unroll
            for (int i = 0; i < 2; i++) {
                const int mB = warpRow + i * 16;
                split_tf32(As[buf][aIdx(mB + g    , kc    )], ah[i][0], al[i][0]);
                split_tf32(As[buf][aIdx(mB + g + 8, kc    )], ah[i][1], al[i][1]);
                split_tf32(As[buf][aIdx(mB + g    , kc + 4)], ah[i][2], al[i][2]);
                split_tf32(As[buf][aIdx(mB + g + 8, kc + 4)], ah[i][3], al[i][3]);
            }
            #pragma unroll
            for (int j = 0; j < 4; j++) {
                const int nB = warpCol + j * 8 + g;
                split_tf32(Bs[buf][bIdx(kc    , nB)], bh[j][0], bl[j][0]);
                split_tf32(Bs[buf][bIdx(kc + 4, nB)], bh[j][1], bl[j][1]);
            }
            #pragma unroll
            for (int i = 0; i < 2; i++)
                #pragma unroll
                for (int j = 0; j < 4; j++) mma_tf32(acc[i][j], ah[i], bh[j]);
            #pragma unroll
            for (int i = 0; i < 2; i++)
                #pragma unroll
                for (int j = 0; j < 4; j++) mma_tf32(acc[i][j], ah[i], bl[j]);
            #pragma unroll
            for (int i = 0; i < 2; i++)
                #pragma unroll
                for (int j = 0; j < 4; j++) mma_tf32(acc[i][j], al[i], bh[j]);
        }
        __syncthreads();
        buf ^= 1;
    }

    float alpha = 0.f, lr = 0.f, decay = 0.f;
    if constexpr (EPI == 4) {
        alpha = sigmoid_f(*pa);
        lr    = sigmoid_f(*pl);
        decay = sigmoid_f(*pd);
    }

    #pragma unroll
    for (int i = 0; i < 2; i++) {
        const int rA = row0 + warpRow + i * 16 + g;
        #pragma unroll
        for (int j = 0; j < 4; j++) {
            const int cA = col0 + warpCol + j * 8 + 2 * t4;
            #pragma unroll
            for (int r = 0; r < 4; r++) {
                const int m = rA + (r >= 2 ? 8 : 0);
                const int n = cA + (r & 1);
                const size_t ci = (size_t)m * ldc + n;
                const float v = acc[i][j][r];
                if constexpr (EPI == 0) {
                    C[ci] = v;
                } else if constexpr (EPI == 1) {
                    C[ci] = v;
                    aux3[ci] = gelu_f(v);
                } else if constexpr (EPI == 2) {
                    C[ci] = (v - aux1[(size_t)m * ldaux + n]) * LOSS_SCALE;
                } else if constexpr (EPI == 3) {
                    C[ci] = v * gelu_grad(aux1[(size_t)m * ldaux + n]);
                } else if constexpr (EPI == 4) {
                    float s = decay * aux3[ci] - lr * v;
                    aux3[ci] = s;                                  // S update (in place)
                    aux4[ci] = (1.0f - alpha) * aux1[ci] + s;      // Wnew = (1-a)*Wold + S
                } else if constexpr (EPI == 5) {
                    C[ci] = gelu_f(v);
                } else if constexpr (EPI == 6) {
                    // m = b*4096 + c*256 + r  ->  out row = (c*BATCH+b)*256 + r
                    int bb = m >> 12;
                    int cc = (m >> 8) & (NCHUNK - 1);
                    int rr = m & (CHUNK - 1);
                    size_t orow = ((size_t)(cc * BATCH + bb) << 8) + rr;
                    C[orow * ldc + n] = v;
                }
            }
        }
    }
}

// ---------------- host driver (fork/join stream overlap inside graph) ----------------
extern "C" void kernel_launch(void* const* d_in, const int* in_sizes, int n_in,
                              void* d_out, int out_size) {
    const float* x     = (const float*)d_in[0];
    const float* w_q   = (const float*)d_in[1];
    const float* w_k   = (const float*)d_in[2];
    const float* w_v   = (const float*)d_in[3];
    const float* mw1   = (const float*)d_in[4];
    const float* mw2   = (const float*)d_in[5];
    const float* p_al  = (const float*)d_in[6];
    const float* p_lr  = (const float*)d_in[7];
    const float* p_dec = (const float*)d_in[8];
    float* out = (float*)d_out;

    float *W1, *W2a, *W2b, *S1, *S2, *WKV, *KV, *H, *Abuf, *DP, *DH, *Q, *AQ;
    cudaGetSymbolAddress((void**)&W1,   g_W1);
    cudaGetSymbolAddress((void**)&W2a,  g_W2a);
    cudaGetSymbolAddress((void**)&W2b,  g_W2b);
    cudaGetSymbolAddress((void**)&S1,   g_S1);
    cudaGetSymbolAddress((void**)&S2,   g_S2);
    cudaGetSymbolAddress((void**)&WKV,  g_WKV);
    cudaGetSymbolAddress((void**)&KV,   g_kv);
    cudaGetSymbolAddress((void**)&H,    g_h);
    cudaGetSymbolAddress((void**)&Abuf, g_a);
    cudaGetSymbolAddress((void**)&DP,   g_dp);
    cudaGetSymbolAddress((void**)&DH,   g_dh);
    cudaGetSymbolAddress((void**)&Q,    g_q);
    cudaGetSymbolAddress((void**)&AQ,   g_aq);
    float* W2buf[2] = { W2a, W2b };

    // one-time resources (handles only; created outside graph capture)
    static cudaStream_t s2 = nullptr;
    static cudaEvent_t evFork, evQ, evKV[NCHUNK], evDP[NCHUNK], evG2[NCHUNK];
    if (!s2) {
        cudaStreamCreateWithFlags(&s2, cudaStreamNonBlocking);
        cudaEventCreateWithFlags(&evFork, cudaEventDisableTiming);
        cudaEventCreateWithFlags(&evQ,    cudaEventDisableTiming);
        for (int i = 0; i < NCHUNK; i++) {
            cudaEventCreateWithFlags(&evKV[i], cudaEventDisableTiming);
            cudaEventCreateWithFlags(&evDP[i], cudaEventDisableTiming);
            cudaEventCreateWithFlags(&evG2[i], cudaEventDisableTiming);
        }
    }

    init_kernel<<<(D1 * D2 + 255) / 256, 256>>>(mw1, mw2, w_k, w_v);

    // kv for chunk 0 on main stream (chain needs it immediately)
    gemm3<false, false, 6><<<dim3(D2 / BN, 16), 128>>>(
        x, WKV, KV, D1, D1, D2, D2, 0, nullptr, nullptr, nullptr,
        nullptr, nullptr, nullptr, 0);

    // fork side stream: kv chunks 1..15 + q, concurrent with the chain
    cudaEventRecord(evFork, 0);
    cudaStreamWaitEvent(s2, evFork, 0);
    for (int c = 1; c < NCHUNK; c++) {
        gemm3<false, false, 6><<<dim3(D2 / BN, 16), 128, 0, s2>>>(
            x, WKV, KV, D1, D1, D2, D2, 0, nullptr, nullptr, nullptr,
            nullptr, nullptr, nullptr, c);
        cudaEventRecord(evKV[c], s2);
    }
    gemm3<false, false, 0><<<dim3(D1 / BN, TOTROWS / BM), 128, 0, s2>>>(
        x, w_q, Q, D1, D1, D1, D1, 0, nullptr, nullptr, nullptr,
        nullptr, nullptr, nullptr, 0);
    cudaEventRecord(evQ, s2);

    for (int c = 0; c < NCHUNK; c++) {
        const float* KVc = KV + (size_t)c * NROWS * D2;
        float* W2o = W2buf[c & 1];
        float* W2n = W2buf[(c + 1) & 1];

        if (c > 0) {
            cudaStreamWaitEvent(0, evKV[c], 0);     // kv for this chunk ready
            cudaStreamWaitEvent(0, evG2[c - 1], 0); // W2 updated; Abuf/DP free to overwrite
        }

        // h = k @ W1 ; a = gelu(h)
        gemm3<false, false, 1><<<dim3(D2 / BN, NROWS / BM), 128>>>(
            KVc, W1, H, D1, D2, D2, D2, 0, nullptr, Abuf, nullptr,
            nullptr, nullptr, nullptr, 0);

        // dpred = (a @ W2o - v) * 2/(N*D)
        gemm3<false, false, 2><<<dim3(D1 / BN, NROWS / BM), 128>>>(
            Abuf, W2o, DP, D2, D2, D1, D1, D2, KVc + D1, nullptr, nullptr,
            nullptr, nullptr, nullptr, 0);
        cudaEventRecord(evDP[c], 0);

        // g2 = a^T @ dpred -> S2 update, W2n = (1-a)*W2o + S2   (side stream, overlaps dh+g1)
        cudaStreamWaitEvent(s2, evDP[c], 0);
        gemm3<true, false, 4><<<dim3(D1 / BN, D2 / BM), 128, 0, s2>>>(
            Abuf, DP, nullptr, NROWS, D2, D1, D1, 0, W2o, S2, W2n,
            p_al, p_lr, p_dec, 0);
        cudaEventRecord(evG2[c], s2);

        // dh = (dpred @ W2o^T) * gelu'(h)
        gemm3<false, true, 3><<<dim3(D2 / BN, NROWS / BM), 128>>>(
            DP, W2o, DH, D1, D1, D1, D2, D2, H, nullptr, nullptr,
            nullptr, nullptr, nullptr, 0);

        // g1 = k^T @ dh -> S1 update, W1 = (1-a)*W1 + S1  (in place)
        gemm3<true, false, 4><<<dim3(D2 / BN, D1 / BM), 128>>>(
            KVc, DH, nullptr, NROWS, D2, D2, D2, 0, W1, S1, W1,
            p_al, p_lr, p_dec, 0);
    }

    // join: final W2 (in W2buf[0] after 16 updates) + q
    cudaStreamWaitEvent(0, evG2[NCHUNK - 1], 0);
    cudaStreamWaitEvent(0, evQ, 0);

    // aq = gelu(q @ W1)
    gemm3<false, false, 5><<<dim3(D2 / BN, TOTROWS / BM), 128>>>(
        Q, W1, AQ, D1, D1, D2, D2, 0, nullptr, nullptr, nullptr,
        nullptr, nullptr, nullptr, 0);

    // out = aq @ W2_final
    gemm3<false, false, 0><<<dim3(D1 / BN, TOTROWS / BM), 128>>>(
        AQ, W2buf[0], out, D2, D2, D1, D1, 0, nullptr, nullptr, nullptr,
        nullptr, nullptr, nullptr, 0);
}

// round 13
// speedup vs baseline: 1.4937x; 1.4937x over previous
#include <cuda_runtime.h>
#include <math.h>
#include <stdint.h>

// ---------------- problem constants ----------------
#define D1      512
#define D2      1024
#define SEQLEN  4096
#define CHUNK   256
#define NCHUNK  16
#define BATCH   4
#define NROWS   (BATCH*CHUNK)          // 1024 rows per chunk
#define TOTROWS (BATCH*SEQLEN)         // 16384
#define LOSS_SCALE (2.0f/((float)NROWS*(float)D1))

// ---------------- device scratch ----------------
__device__ float g_W1 [D1*D2];
__device__ float g_W2a[D2*D1];         // W2 ping
__device__ float g_W2b[D2*D1];         // W2 pong
__device__ float g_W2Ta[D1*D2];        // W2^T ping  [D1][D2]
__device__ float g_W2Tb[D1*D2];        // W2^T pong
__device__ float g_S1 [D1*D2];
__device__ float g_S2 [D2*D1];
__device__ float g_WKV[D1*D2];
__device__ float g_kv [NCHUNK*NROWS*D2];   // chunk-major: [c][b][r][D2]; 0..511=k, 512..1023=v
__device__ float g_kT [NCHUNK*D1*NROWS];   // k^T per chunk: [c][d1][row]
__device__ float g_h  [NROWS*D2];
__device__ float g_a  [NROWS*D2];
__device__ float g_dp [NROWS*D1];
__device__ float g_dh [NROWS*D2];
__device__ float g_q  [TOTROWS*D1];
__device__ float g_aq [TOTROWS*D2];

// ---------------- math helpers ----------------
__device__ __forceinline__ float gelu_f(float x) {
    return 0.5f * x * (1.0f + erff(x * 0.70710678118654752f));
}
__device__ __forceinline__ float gelu_grad(float x) {
    float cdf = 0.5f * (1.0f + erff(x * 0.70710678118654752f));
    float pdf = 0.3989422804014327f * expf(-0.5f * x * x);
    return cdf + x * pdf;
}
__device__ __forceinline__ float sigmoid_f(float x) { return 1.0f / (1.0f + expf(-x)); }

__device__ __forceinline__ void split_tf32(float v, uint32_t& hi, uint32_t& lo) {
    uint32_t h;
    asm("cvt.rna.tf32.f32 %0, %1;" : "=r"(h) : "f"(v));
    float lf = v - __uint_as_float(h);
    asm("cvt.rna.tf32.f32 %0, %1;" : "=r"(lo) : "f"(lf));
    hi = h;
}
__device__ __forceinline__ void mma_tf32(float* c, const uint32_t* a, const uint32_t* b) {
    asm volatile(
        "mma.sync.aligned.m16n8k8.row.col.f32.tf32.tf32.f32 "
        "{%0,%1,%2,%3}, {%4,%5,%6,%7}, {%8,%9}, {%0,%1,%2,%3};"
        : "+f"(c[0]), "+f"(c[1]), "+f"(c[2]), "+f"(c[3])
        : "r"(a[0]), "r"(a[1]), "r"(a[2]), "r"(a[3]), "r"(b[0]), "r"(b[1]));
}

// cp.async helpers
__device__ __forceinline__ void cp16(void* s, const void* g) {
    uint32_t sa = (uint32_t)__cvta_generic_to_shared(s);
    asm volatile("cp.async.ca.shared.global [%0], [%1], 16;\n" :: "r"(sa), "l"(g));
}
__device__ __forceinline__ void cp4(void* s, const void* g) {
    uint32_t sa = (uint32_t)__cvta_generic_to_shared(s);
    asm volatile("cp.async.ca.shared.global [%0], [%1], 4;\n" :: "r"(sa), "l"(g));
}
#define CP_COMMIT() asm volatile("cp.async.commit_group;\n" ::: "memory")
#define CP_WAIT(n)  asm volatile("cp.async.wait_group %0;\n" :: "n"(n) : "memory")

// ---------------- init ----------------
__global__ void init_kernel(const float* __restrict__ mw1, const float* __restrict__ mw2,
                            const float* __restrict__ wk,  const float* __restrict__ wv) {
    int i = blockIdx.x * blockDim.x + threadIdx.x;
    if (i < D1 * D2) {
        g_W1[i]  = mw1[i];  g_S1[i] = 0.0f;
        g_W2a[i] = mw2[i];  g_S2[i] = 0.0f;
        {   // W2^T init: mw2 is [D2][D1]; W2T[n][m] = mw2[m][n]
            int m = i / D1, n = i % D1;
            g_W2Ta[(size_t)n * D2 + m] = mw2[i];
        }
        int d = i / D2, j = i % D2;
        g_WKV[i] = (j < D1) ? wk[d * D1 + j] : wv[d * D1 + (j - D1)];
    }
}

// ---------------- tiling ----------------
#define BM 64
#define BN 64
#define BK 32
#define APAD 4   // A row = 36 words
#define BPAD 8   // B row = 72 words

// ---------------- GEMM: 3xTF32, cp.async double buffer (R10-proven core, verbatim) ----------------
// op(A)[M,K] * op(B)[K,N]
// EPI: 0 C=acc | 1 C=acc, aux3=gelu(acc) | 2 C=(acc-aux1)*LOSS_SCALE | 3 C=acc*gelu'(aux1)
//      4 S(aux3)=decay*S-lr*acc; Wnew(aux4)=(1-a)*Wold(aux1)+S; auxT?=Wnew^T
//      5 C=gelu(acc) | 6 kv chunk-major permute; auxT?=k^T
template<bool TA, bool TB, int EPI>
__global__ __launch_bounds__(128)
void gemm3(const float* __restrict__ A, const float* __restrict__ B, float* __restrict__ C,
           int K, int lda, int ldb, int ldc, int ldaux,
           const float* __restrict__ aux1, float* __restrict__ aux3, float* __restrict__ aux4,
           float* __restrict__ auxT,
           const float* __restrict__ pa, const float* __restrict__ pl, const float* __restrict__ pd,
           int cidx) {
    __shared__ float As[2][BM][BK + APAD];
    __shared__ float Bs[2][BK][BN + BPAD];

    int by = blockIdx.y;
    if constexpr (EPI == 6) by = (by >> 2) * 64 + cidx * 4 + (by & 3);  // rows of chunk cidx
    const int row0 = by * BM;
    const int col0 = blockIdx.x * BN;
    const int t    = threadIdx.x;
    const int lane = t & 31;
    const int warp = t >> 5;
    const int warpRow = (warp >> 1) * 32;
    const int warpCol = (warp & 1) * 32;
    const int g  = lane >> 2;
    const int t4 = lane & 3;

    auto stage = [&](int b, int k0) {
        #pragma unroll
        for (int it = 0; it < 4; it++) {
            int f = t + it * 128;
            if constexpr (!TA) {
                int m = f >> 3, kk0 = (f & 7) * 4;
                cp16(&As[b][m][kk0], &A[(size_t)(row0 + m) * lda + (k0 + kk0)]);
            } else {
                int m0 = (f & 15) * 4, kk = f >> 4;
                const float* src = &A[(size_t)(k0 + kk) * lda + (row0 + m0)];
                cp4(&As[b][m0 + 0][kk], src + 0);
                cp4(&As[b][m0 + 1][kk], src + 1);
                cp4(&As[b][m0 + 2][kk], src + 2);
                cp4(&As[b][m0 + 3][kk], src + 3);
            }
        }
        #pragma unroll
        for (int it = 0; it < 4; it++) {
            int f = t + it * 128;
            if constexpr (!TB) {
                int n0 = (f & 15) * 4, kk = f >> 4;
                cp16(&Bs[b][kk][n0], &B[(size_t)(k0 + kk) * ldb + (col0 + n0)]);
            } else {
                int kk0 = (f & 7) * 4, n = f >> 3;
                const float* src = &B[(size_t)(col0 + n) * ldb + (k0 + kk0)];
                cp4(&Bs[b][kk0 + 0][n], src + 0);
                cp4(&Bs[b][kk0 + 1][n], src + 1);
                cp4(&Bs[b][kk0 + 2][n], src + 2);
                cp4(&Bs[b][kk0 + 3][n], src + 3);
            }
        }
    };

    float acc[2][4][4];
    #pragma unroll
    for (int i = 0; i < 2; i++)
        #pragma unroll
        for (int j = 0; j < 4; j++)
            #pragma unroll
            for (int r = 0; r < 4; r++) acc[i][j][r] = 0.0f;

    const int KITER = K / BK;
    stage(0, 0);
    CP_COMMIT();
    int buf = 0;
    for (int it = 0; it < KITER; ++it) {
        if (it + 1 < KITER) {
            stage(buf ^ 1, (it + 1) * BK);
            CP_COMMIT();
            CP_WAIT(1);
        } else {
            CP_WAIT(0);
        }
        __syncthreads();

        #pragma unroll
        for (int ks = 0; ks < 4; ks++) {
            const int kc = ks * 8 + t4;
            uint32_t ah[2][4], al[2][4], bh[4][2], bl[4][2];
            #pragma unroll
            for (int i = 0; i < 2; i++) {
                const int mB = warpRow + i * 16;
                split_tf32(As[buf][mB + g    ][kc    ], ah[i][0], al[i][0]);
                split_tf32(As[buf][mB + g + 8][kc    ], ah[i][1], al[i][1]);
                split_tf32(As[buf][mB + g    ][kc + 4], ah[i][2], al[i][2]);
                split_tf32(As[buf][mB + g + 8][kc + 4], ah[i][3], al[i][3]);
            }
            #pragma unroll
            for (int j = 0; j < 4; j++) {
                const int nB = warpCol + j * 8 + g;
                split_tf32(Bs[buf][kc    ][nB], bh[j][0], bl[j][0]);
                split_tf32(Bs[buf][kc + 4][nB], bh[j][1], bl[j][1]);
            }
            #pragma unroll
            for (int i = 0; i < 2; i++)
                #pragma unroll
                for (int j = 0; j < 4; j++) mma_tf32(acc[i][j], ah[i], bh[j]);
            #pragma unroll
            for (int i = 0; i < 2; i++)
                #pragma unroll
                for (int j = 0; j < 4; j++) mma_tf32(acc[i][j], ah[i], bl[j]);
            #pragma unroll
            for (int i = 0; i < 2; i++)
                #pragma unroll
                for (int j = 0; j < 4; j++) mma_tf32(acc[i][j], al[i], bh[j]);
        }
        __syncthreads();
        buf ^= 1;
    }

    float alpha = 0.f, lr = 0.f, decay = 0.f;
    if constexpr (EPI == 4) {
        alpha = sigmoid_f(*pa);
        lr    = sigmoid_f(*pl);
        decay = sigmoid_f(*pd);
    }

    #pragma unroll
    for (int i = 0; i < 2; i++) {
        const int rA = row0 + warpRow + i * 16 + g;
        #pragma unroll
        for (int j = 0; j < 4; j++) {
            const int cA = col0 + warpCol + j * 8 + 2 * t4;
            #pragma unroll
            for (int r = 0; r < 4; r++) {
                const int m = rA + (r >= 2 ? 8 : 0);
                const int n = cA + (r & 1);
                const size_t ci = (size_t)m * ldc + n;
                const float v = acc[i][j][r];
                if constexpr (EPI == 0) {
                    C[ci] = v;
                } else if constexpr (EPI == 1) {
                    C[ci] = v;
                    aux3[ci] = gelu_f(v);
                } else if constexpr (EPI == 2) {
                    C[ci] = (v - aux1[(size_t)m * ldaux + n]) * LOSS_SCALE;
                } else if constexpr (EPI == 3) {
                    C[ci] = v * gelu_grad(aux1[(size_t)m * ldaux + n]);
                } else if constexpr (EPI == 4) {
                    float s = decay * aux3[ci] - lr * v;
                    aux3[ci] = s;                                  // S update (in place)
                    float w = (1.0f - alpha) * aux1[ci] + s;       // Wnew = (1-a)*Wold + S
                    aux4[ci] = w;
                    if (auxT) auxT[(size_t)n * ldaux + m] = w;     // Wnew^T (scatter, hidden stream)
                } else if constexpr (EPI == 5) {
                    C[ci] = gelu_f(v);
                } else if constexpr (EPI == 6) {
                    // m = b*4096 + c*256 + r  ->  out row = (c*BATCH+b)*256 + r
                    int bb = m >> 12;
                    int cc = (m >> 8) & (NCHUNK - 1);
                    int rr = m & (CHUNK - 1);
                    int lrow = bb * CHUNK + rr;                 // chunk-local row
                    size_t orow = ((size_t)cc * BATCH << 8) + ((size_t)bb << 8) + rr;
                    C[orow * ldc + n] = v;
                    if (n < D1) auxT[((size_t)cc * D1 + n) * NROWS + lrow] = v;  // k^T
                }
            }
        }
    }
}

// ---------------- host driver (fork/join stream overlap inside graph) ----------------
extern "C" void kernel_launch(void* const* d_in, const int* in_sizes, int n_in,
                              void* d_out, int out_size) {
    const float* x     = (const float*)d_in[0];
    const float* w_q   = (const float*)d_in[1];
    const float* w_k   = (const float*)d_in[2];
    const float* w_v   = (const float*)d_in[3];
    const float* mw1   = (const float*)d_in[4];
    const float* mw2   = (const float*)d_in[5];
    const float* p_al  = (const float*)d_in[6];
    const float* p_lr  = (const float*)d_in[7];
    const float* p_dec = (const float*)d_in[8];
    float* out = (float*)d_out;

    float *W1, *W2a, *W2b, *W2Ta, *W2Tb, *S1, *S2, *WKV, *KV, *KT, *H, *Abuf, *DP, *DH, *Q, *AQ;
    cudaGetSymbolAddress((void**)&W1,   g_W1);
    cudaGetSymbolAddress((void**)&W2a,  g_W2a);
    cudaGetSymbolAddress((void**)&W2b,  g_W2b);
    cudaGetSymbolAddress((void**)&W2Ta, g_W2Ta);
    cudaGetSymbolAddress((void**)&W2Tb, g_W2Tb);
    cudaGetSymbolAddress((void**)&S1,   g_S1);
    cudaGetSymbolAddress((void**)&S2,   g_S2);
    cudaGetSymbolAddress((void**)&WKV,  g_WKV);
    cudaGetSymbolAddress((void**)&KV,   g_kv);
    cudaGetSymbolAddress((void**)&KT,   g_kT);
    cudaGetSymbolAddress((void**)&H,    g_h);
    cudaGetSymbolAddress((void**)&Abuf, g_a);
    cudaGetSymbolAddress((void**)&DP,   g_dp);
    cudaGetSymbolAddress((void**)&DH,   g_dh);
    cudaGetSymbolAddress((void**)&Q,    g_q);
    cudaGetSymbolAddress((void**)&AQ,   g_aq);
    float* W2buf[2]  = { W2a,  W2b  };
    float* W2Tbuf[2] = { W2Ta, W2Tb };

    // one-time resources (handles only; created outside graph capture)
    static cudaStream_t s2 = nullptr;
    static cudaEvent_t evFork, evQ, evKV[NCHUNK], evDP[NCHUNK], evG2[NCHUNK];
    if (!s2) {
        cudaStreamCreateWithFlags(&s2, cudaStreamNonBlocking);
        cudaEventCreateWithFlags(&evFork, cudaEventDisableTiming);
        cudaEventCreateWithFlags(&evQ,    cudaEventDisableTiming);
        for (int i = 0; i < NCHUNK; i++) {
            cudaEventCreateWithFlags(&evKV[i], cudaEventDisableTiming);
            cudaEventCreateWithFlags(&evDP[i], cudaEventDisableTiming);
            cudaEventCreateWithFlags(&evG2[i], cudaEventDisableTiming);
        }
    }

    init_kernel<<<(D1 * D2 + 255) / 256, 256>>>(mw1, mw2, w_k, w_v);

    // kv for chunk 0 on main stream (chain needs it immediately); also writes k^T chunk 0
    gemm3<false, false, 6><<<dim3(D2 / BN, 16), 128>>>(
        x, WKV, KV, D1, D1, D2, D2, 0, nullptr, nullptr, nullptr, KT,
        nullptr, nullptr, nullptr, 0);

    // fork side stream: kv chunks 1..15 + q, concurrent with the chain
    cudaEventRecord(evFork, 0);
    cudaStreamWaitEvent(s2, evFork, 0);
    for (int c = 1; c < NCHUNK; c++) {
        gemm3<false, false, 6><<<dim3(D2 / BN, 16), 128, 0, s2>>>(
            x, WKV, KV, D1, D1, D2, D2, 0, nullptr, nullptr, nullptr, KT,
            nullptr, nullptr, nullptr, c);
        cudaEventRecord(evKV[c], s2);
    }
    gemm3<false, false, 0><<<dim3(D1 / BN, TOTROWS / BM), 128, 0, s2>>>(
        x, w_q, Q, D1, D1, D1, D1, 0, nullptr, nullptr, nullptr, nullptr,
        nullptr, nullptr, nullptr, 0);
    cudaEventRecord(evQ, s2);

    for (int c = 0; c < NCHUNK; c++) {
        const float* KVc = KV + (size_t)c * NROWS * D2;
        const float* KTc = KT + (size_t)c * D1 * NROWS;
        float* W2o  = W2buf [c & 1];
        float* W2n  = W2buf [(c + 1) & 1];
        float* W2To = W2Tbuf[c & 1];
        float* W2Tn = W2Tbuf[(c + 1) & 1];

        if (c > 0) {
            cudaStreamWaitEvent(0, evKV[c], 0);     // kv + k^T for this chunk ready
            cudaStreamWaitEvent(0, evG2[c - 1], 0); // W2/W2^T updated; Abuf/DP free
        }

        // h = k @ W1 ; a = gelu(h)
        gemm3<false, false, 1><<<dim3(D2 / BN, NROWS / BM), 128>>>(
            KVc, W1, H, D1, D2, D2, D2, 0, nullptr, Abuf, nullptr, nullptr,
            nullptr, nullptr, nullptr, 0);

        // dpred = (a @ W2o - v) * 2/(N*D)
        gemm3<false, false, 2><<<dim3(D1 / BN, NROWS / BM), 128>>>(
            Abuf, W2o, DP, D2, D2, D1, D1, D2, KVc + D1, nullptr, nullptr, nullptr,
            nullptr, nullptr, nullptr, 0);
        cudaEventRecord(evDP[c], 0);

        // g2 = a^T @ dpred -> S2, W2n = (1-a)*W2o + S2, plus W2Tn   (side stream)
        cudaStreamWaitEvent(s2, evDP[c], 0);
        gemm3<true, false, 4><<<dim3(D1 / BN, D2 / BM), 128, 0, s2>>>(
            Abuf, DP, nullptr, NROWS, D2, D1, D1, D2, W2o, S2, W2n, W2Tn,
            p_al, p_lr, p_dec, 0);
        cudaEventRecord(evG2[c], s2);

        // dh = (dpred @ W2To) * gelu'(h)   — fast path, no transposed staging
        gemm3<false, false, 3><<<dim3(D2 / BN, NROWS / BM), 128>>>(
            DP, W2To, DH, D1, D1, D2, D2, D2, H, nullptr, nullptr, nullptr,
            nullptr, nullptr, nullptr, 0);

        // g1 = kT @ dh -> S1, W1 = (1-a)*W1 + S1   — fast path via materialized k^T
        gemm3<false, false, 4><<<dim3(D2 / BN, D1 / BM), 128>>>(
            KTc, DH, nullptr, NROWS, NROWS, D2, D2, D2, W1, S1, W1, nullptr,
            p_al, p_lr, p_dec, 0);
    }

    // join: final W2 (in W2buf[0] after 16 updates) + q
    cudaStreamWaitEvent(0, evG2[NCHUNK - 1], 0);
    cudaStreamWaitEvent(0, evQ, 0);

    // aq = gelu(q @ W1)
    gemm3<false, false, 5><<<dim3(D2 / BN, TOTROWS / BM), 128>>>(
        Q, W1, AQ, D1, D1, D2, D2, 0, nullptr, nullptr, nullptr, nullptr,
        nullptr, nullptr, nullptr, 0);

    // out = aq @ W2_final
    gemm3<false, false, 0><<<dim3(D1 / BN, TOTROWS / BM), 128>>>(
        AQ, W2buf[0], out, D2, D2, D1, D1, 0, nullptr, nullptr, nullptr, nullptr,
        nullptr, nullptr, nullptr, 0);
}